// round 5
// baseline (speedup 1.0000x reference)
#include <cuda_runtime.h>
#include <math.h>

#define FRAME      480
#define NHALF      480
#define FREQ       481
#define NB_ERB     32
#define NB_DF      96
#define ALPHA_F    0.99f
#define ONE_MINUS_ALPHA 0.01f
#define WNORM_F    (1.0f/960.0f)
#define T_MAX      65536
#define CHUNKS     1024
#define PI_F       3.14159265358979f

typedef unsigned long long ull;

// ---------------- packed f32x2 helpers ----------------
__device__ __forceinline__ ull pk(float x, float y){ ull r; asm("mov.b64 %0, {%1, %2};" : "=l"(r) : "f"(x), "f"(y)); return r; }
__device__ __forceinline__ void up(ull a, float& x, float& y){ asm("mov.b64 {%0, %1}, %2;" : "=f"(x), "=f"(y) : "l"(a)); }
__device__ __forceinline__ ull padd(ull a, ull b){ ull r; asm("add.rn.f32x2 %0, %1, %2;" : "=l"(r) : "l"(a), "l"(b)); return r; }
__device__ __forceinline__ ull psub(ull a, ull b){ ull r; asm("sub.rn.f32x2 %0, %1, %2;" : "=l"(r) : "l"(a), "l"(b)); return r; }
__device__ __forceinline__ ull pmul(ull a, ull b){ ull r; asm("mul.rn.f32x2 %0, %1, %2;" : "=l"(r) : "l"(a), "l"(b)); return r; }
__device__ __forceinline__ ull pfma(ull a, ull b, ull c){ ull r; asm("fma.rn.f32x2 %0, %1, %2, %3;" : "=l"(r) : "l"(a), "l"(b), "l"(c)); return r; }

// complex mul by constant (c,s):  a * (c + i s)
__device__ __forceinline__ ull cmulc(ull a, float c, float s){
    float ax, ay; up(a, ax, ay);
    return pfma(pk(ay, ay), pk(-s, c), pmul(pk(ax, ax), pk(c, s)));
}
// complex mul by table twiddle stored as t0=(c,s), t1=(-s,c)
__device__ __forceinline__ ull cmult(ull a, ull t0, ull t1){
    float ax, ay; up(a, ax, ay);
    return pfma(pk(ay, ay), t1, pmul(pk(ax, ax), t0));
}

// ---------------- static device scratch ----------------
__device__ float4 g_tw480[15*32];      // (c,s,-s,c): W_480^{l*k1}, [k1*32+l]
__device__ float4 g_shtw[5*32];        // per-stage per-lane shuffle twiddles
__device__ float2 g_win2[NHALF];       // window pairs
__device__ float4 g_rec[FREQ];         // (c,s,-s,c): cis(-pi*k/480)
__device__ float  g_erb[T_MAX * NB_ERB];
__device__ float  g_carryE[CHUNKS * NB_ERB];
__device__ float  g_inE[CHUNKS * NB_ERB];
__device__ float  g_carryS[CHUNKS * NB_DF];
__device__ float  g_inS[CHUNKS * NB_DF];

__constant__ int c_bandOff[NB_ERB] =
 {0,2,4,6,8,10,12,14,16,18,20,22,24,26,31,36,43,50,58,68,80,93,108,126,146,170,198,229,266,308,358,414};
__constant__ int c_bandCnt[NB_ERB] =
 {2,2,2,2,2,2,2,2,2,2,2,2,2,5,5,7,7,8,10,12,13,15,18,20,24,28,31,37,42,50,56,67};

// ---------------- Winograd small DFTs (packed) ----------------
__device__ __forceinline__ void dft3p(ull x0, ull x1, ull x2, ull& X0, ull& X1, ull& X2){
    ull t1 = padd(x1, x2);
    ull t2 = psub(x1, x2);
    X0 = padd(x0, t1);
    ull m = pfma(pk(-0.5f,-0.5f), t1, x0);
    ull v = pmul(pk(0.86602540378f,0.86602540378f), t2);
    float mx,my,vx,vy; up(m,mx,my); up(v,vx,vy);
    X1 = pk(mx+vy, my-vx);
    X2 = pk(mx-vy, my+vx);
}
__device__ __forceinline__ void dft5p(ull x0, ull x1, ull x2, ull x3, ull x4,
                                      ull& X0, ull& X1, ull& X2, ull& X3, ull& X4){
    const float s1 = 0.95105651630f, s2 = 0.58778525229f;
    ull t1 = padd(x1, x4), t2 = psub(x1, x4);
    ull t3 = padd(x2, x3), t4 = psub(x2, x3);
    ull t5 = padd(t1, t3), t6 = psub(t1, t3);
    X0 = padd(x0, t5);
    ull p = pfma(pk(-0.25f,-0.25f), t5, x0);
    ull q = pmul(pk(0.55901699437f,0.55901699437f), t6);
    ull P = padd(p, q), Q = psub(p, q);
    ull R = pfma(pk(s2,s2), t4, pmul(pk(s1,s1), t2));
    ull S = pfma(pk(-s1,-s1), t4, pmul(pk(s2,s2), t2));
    float Px,Py,Qx,Qy,Rx,Ry,Sx,Sy;
    up(P,Px,Py); up(Q,Qx,Qy); up(R,Rx,Ry); up(S,Sx,Sy);
    X1 = pk(Px+Ry, Py-Rx);
    X4 = pk(Px-Ry, Py+Rx);
    X2 = pk(Qx+Sy, Qy-Sx);
    X3 = pk(Qx-Sy, Qy+Sx);
}

// ---------------- init tables ----------------
__global__ void init_tables(){
    int tid = blockIdx.x * blockDim.x + threadIdx.x;
    int nth = gridDim.x * blockDim.x;
    for (int idx = tid; idx < 15*32; idx += nth){
        int k1 = idx / 32, l = idx % 32;
        float ang = -2.0f * PI_F * (float)(l * k1) / 480.0f;
        float sv, cv; sincosf(ang, &sv, &cv);
        g_tw480[idx] = make_float4(cv, sv, -sv, cv);
    }
    for (int idx = tid; idx < 5*32; idx += nth){
        int j = idx / 32, l = idx % 32;
        int h = 16 >> j;
        float sv = 0.f, cv = 1.f;
        if (l & h){
            float ang = -2.0f * PI_F * (float)(l & (h-1)) / (float)(2*h);
            sincosf(ang, &sv, &cv);
        }
        g_shtw[idx] = make_float4(cv, sv, -sv, cv);
    }
    for (int j = tid; j < NHALF; j += nth){
        float a0 = sinf(0.5f * PI_F * (2*j + 0.5f) / 480.0f);
        float a1 = sinf(0.5f * PI_F * (2*j + 1.5f) / 480.0f);
        g_win2[j] = make_float2(sinf(0.5f * PI_F * a0 * a0), sinf(0.5f * PI_F * a1 * a1));
    }
    for (int k = tid; k < FREQ; k += nth){
        float ang = -PI_F * (float)k / 480.0f;
        float sv, cv; sincosf(ang, &sv, &cv);
        g_rec[k] = make_float4(cv, sv, -sv, cv);
    }
}

// ---------------- FFT: one warp per frame, register-resident, packed math ----------------
__global__ __launch_bounds__(128) void fft_kernel(const float* __restrict__ audio,
                                                  float* __restrict__ out, int T){
    __shared__ float2 sZ[4][NHALF];
    __shared__ float  smag[4][FREQ];
    int w = threadIdx.x >> 5;
    int l = threadIdx.x & 31;
    int t = blockIdx.x * 4 + w;
    if (t >= T) return;

    const float2* audio2 = (const float2*)audio;
    long base2 = ((long)t - 1) * 240;

    // load + window
    ull z[15];
    #pragma unroll
    for (int m = 0; m < 15; m++){
        long i2 = base2 + l + 32*m;
        float2 x = (i2 >= 0) ? audio2[i2] : make_float2(0.f,0.f);
        float2 ww = g_win2[l + 32*m];
        z[m] = pmul(pk(x.x, x.y), pk(ww.x, ww.y));
    }

    // ---- radix-15 (3x5 Winograd)
    ull B[15];
    {
        ull G0[5], G1[5], G2[5];
        #pragma unroll
        for (int b = 0; b < 5; b++)
            dft3p(z[b], z[5+b], z[10+b], G0[b], G1[b], G2[b]);
        // r=0
        dft5p(G0[0],G0[1],G0[2],G0[3],G0[4], B[0],B[3],B[6],B[9],B[12]);
        // r=1 : twiddle W15^b
        G1[1] = cmulc(G1[1],  0.91354545764f, -0.40673664308f);
        G1[2] = cmulc(G1[2],  0.66913060636f, -0.74314482548f);
        G1[3] = cmulc(G1[3],  0.30901699437f, -0.95105651630f);
        G1[4] = cmulc(G1[4], -0.10452846327f, -0.99452189537f);
        dft5p(G1[0],G1[1],G1[2],G1[3],G1[4], B[1],B[4],B[7],B[10],B[13]);
        // r=2 : twiddle W15^{2b}
        G2[1] = cmulc(G2[1],  0.66913060636f, -0.74314482548f);
        G2[2] = cmulc(G2[2], -0.10452846327f, -0.99452189537f);
        G2[3] = cmulc(G2[3], -0.80901699437f, -0.58778525229f);
        G2[4] = cmulc(G2[4], -0.97814760073f,  0.20791169082f);
        dft5p(G2[0],G2[1],G2[2],G2[3],G2[4], B[2],B[5],B[8],B[11],B[14]);
    }

    // ---- four-step twiddle
    #pragma unroll
    for (int k1 = 1; k1 < 15; k1++){
        float4 tw = g_tw480[k1*32 + l];
        B[k1] = cmult(B[k1], pk(tw.x,tw.y), pk(tw.z,tw.w));
    }

    // ---- 32-pt cross-lane DFT: 5 radix-2 DIF shuffle stages
    #pragma unroll
    for (int j = 0; j < 5; j++){
        int h = 16 >> j;
        float sgn = (l & h) ? -1.f : 1.f;
        ull sgn2 = pk(sgn, sgn);
        float4 tw = g_shtw[j*32 + l];
        ull t0 = pk(tw.x,tw.y), t1 = pk(tw.z,tw.w);
        #pragma unroll
        for (int k1 = 0; k1 < 15; k1++){
            float bx, by; up(B[k1], bx, by);
            float px = __shfl_xor_sync(0xffffffffu, bx, h);
            float py = __shfl_xor_sync(0xffffffffu, by, h);
            ull nv = pfma(sgn2, B[k1], pk(px, py));
            B[k1] = cmult(nv, t0, t1);
        }
    }

    // lane l holds Z[k1 + 15*bitrev5(l)]
    int s = ((l&1)<<4) | ((l&2)<<2) | (l&4) | ((l&8)>>2) | ((l&16)>>4);
    float2* Z = sZ[w];
    #pragma unroll
    for (int k1 = 0; k1 < 15; k1++){
        float bx, by; up(B[k1], bx, by);
        Z[15*s + k1] = make_float2(bx, by);
    }
    __syncwarp();

    // ---- real-FFT recombination + spec write + mag2
    float* mg = smag[w];
    float2* out2 = (float2*)out;
    size_t orow = (size_t)t * FREQ;
    for (int k = l; k <= 480; k += 32){
        float2 Zk = Z[(k == 480) ? 0 : k];
        float2 Zc = Z[(480 - k) % 480];
        ull E = pmul(pk(0.5f,0.5f), pk(Zk.x + Zc.x, Zk.y - Zc.y));
        float Dx = Zk.x - Zc.x, Dy = Zk.y + Zc.y;
        ull O = pk(0.5f * Dy, -0.5f * Dx);
        float4 rc = g_rec[k];
        ull X = padd(E, cmult(O, pk(rc.x,rc.y), pk(rc.z,rc.w)));
        X = pmul(pk(WNORM_F, WNORM_F), X);
        float Xx, Xy; up(X, Xx, Xy);
        out2[orow + k] = make_float2(Xx, Xy);
        mg[k] = Xx*Xx + Xy*Xy;
    }
    __syncwarp();

    // ---- erb bands
    {
        int st = c_bandOff[l], n = c_bandCnt[l];
        float acc = 0.0f;
        for (int q = 0; q < n; q++) acc += mg[st + q];
        g_erb[(size_t)t * NB_ERB + l] = 10.0f * log10f(acc / (float)n + 1e-10f);
    }
}

// ---------------- fused chunked scans ----------------
__global__ void pass1(const float* __restrict__ out, int T){
    int w = blockIdx.x * blockDim.x + threadIdx.x;
    int len = T / CHUNKS;
    int totE = CHUNKS * NB_ERB;
    if (w < totE){
        int ch = w % NB_ERB, c = w / NB_ERB;
        const float* x = g_erb + (size_t)c * len * NB_ERB + ch;
        float s = 0.0f;
        for (int i = 0; i < len; i++) s = ALPHA_F * s + ONE_MINUS_ALPHA * x[i * NB_ERB];
        g_carryE[c * NB_ERB + ch] = s;
    } else if (w < totE + CHUNKS * NB_DF){
        int w2 = w - totE;
        int ch = w2 % NB_DF, c = w2 / NB_DF;
        const float* sp = out + (size_t)c * len * 962 + 2 * ch;
        float u = 0.0f;
        for (int i = 0; i < len; i++){
            float xr = sp[i * 962], xi = sp[i * 962 + 1];
            u = ALPHA_F * u + ONE_MINUS_ALPHA * sqrtf(xr*xr + xi*xi);
        }
        g_carryS[c * NB_DF + ch] = u;
    }
}

// parallel affine scan across chunks
__global__ __launch_bounds__(CHUNKS) void pass2(int T){
    __shared__ float sa[CHUNKS];
    __shared__ float sb[CHUNKS];
    int ch = blockIdx.x;
    int c  = threadIdx.x;
    int len = T / CHUNKS;
    float m = __powf(ALPHA_F, (float)len);
    bool isErb = (ch < NB_ERB);
    int cc = isErb ? ch : (ch - NB_ERB);
    float carry = isErb ? g_carryE[c * NB_ERB + cc] : g_carryS[c * NB_DF + cc];

    float a = m, b = carry;
    sa[c] = a; sb[c] = b;
    __syncthreads();
    #pragma unroll
    for (int off = 1; off < CHUNKS; off <<= 1){
        float pa = 0.f, pb = 0.f;
        if (c >= off){ pa = sa[c - off]; pb = sb[c - off]; }
        __syncthreads();
        if (c >= off){ b = a * pb + b; a = a * pa; }
        sa[c] = a; sb[c] = b;
        __syncthreads();
    }
    float Aex = (c == 0) ? 1.f : sa[c-1];
    float Bex = (c == 0) ? 0.f : sb[c-1];
    if (isErb){
        float s0 = -60.0f - 30.0f * (float)cc / 31.0f;
        g_inE[c * NB_ERB + cc] = Aex * s0 + Bex;
    } else {
        float u0 = 0.001f - 0.0009f * (float)cc / 95.0f;
        g_inS[c * NB_DF + cc] = Aex * u0 + Bex;
    }
}

__global__ void pass3(float* __restrict__ out, int T){
    int w = blockIdx.x * blockDim.x + threadIdx.x;
    int len = T / CHUNKS;
    int totE = CHUNKS * NB_ERB;
    if (w < totE){
        int ch = w % NB_ERB, c = w / NB_ERB;
        size_t erb_off = (size_t)T * 962;
        const float* x = g_erb + (size_t)c * len * NB_ERB + ch;
        float* o = out + erb_off + (size_t)c * len * NB_ERB + ch;
        float s = g_inE[c * NB_ERB + ch];
        for (int i = 0; i < len; i++){
            float xv = x[i * NB_ERB];
            s = ALPHA_F * s + ONE_MINUS_ALPHA * xv;
            o[i * NB_ERB] = (xv - s) * 0.025f;
        }
    } else if (w < totE + CHUNKS * NB_DF){
        int w2 = w - totE;
        int ch = w2 % NB_DF, c = w2 / NB_DF;
        size_t sf_off = (size_t)T * 962 + (size_t)T * NB_ERB;
        const float* sp = out + (size_t)c * len * 962 + 2 * ch;
        float* o = out + sf_off + (size_t)c * len * 192 + 2 * ch;
        float u = g_inS[c * NB_DF + ch];
        for (int i = 0; i < len; i++){
            float xr = sp[i * 962], xi = sp[i * 962 + 1];
            u = ALPHA_F * u + ONE_MINUS_ALPHA * sqrtf(xr*xr + xi*xi);
            float r = rsqrtf(u);
            o[i * 192]     = xr * r;
            o[i * 192 + 1] = xi * r;
        }
    }
}

// ---------------- launch ----------------
extern "C" void kernel_launch(void* const* d_in, const int* in_sizes, int n_in,
                              void* d_out, int out_size){
    const float* audio = (const float*)d_in[0];
    float* out = (float*)d_out;
    int T = in_sizes[0] / FRAME;
    if (T > T_MAX) T = T_MAX;
    int scanThreads = CHUNKS * (NB_ERB + NB_DF);

    init_tables<<<8, 256>>>();
    fft_kernel<<<(T + 3) / 4, 128>>>(audio, out, T);
    pass1<<<(scanThreads + 255) / 256, 256>>>(out, T);
    pass2<<<NB_ERB + NB_DF, CHUNKS>>>(T);
    pass3<<<(scanThreads + 255) / 256, 256>>>(out, T);
}

// round 6
// speedup vs baseline: 1.3130x; 1.3130x over previous
#include <cuda_runtime.h>
#include <math.h>

#define FRAME      480
#define NHALF      480
#define FREQ       481
#define NB_ERB     32
#define NB_DF      96
#define ALPHA_F    0.99f
#define ONE_MINUS_ALPHA 0.01f
#define WNORM_F    (1.0f/960.0f)
#define T_MAX      65536
#define CHUNKS     1024
#define PI_F       3.14159265358979f

// ---------------- static device scratch ----------------
__device__ float2 g_tw480[15*32];      // W_480^{l*k1}, [k1*32+l]
__device__ float2 g_shtw[4*32];        // shuffle-stage twiddles (stage 5 is identity)
__device__ float2 g_win2[NHALF];       // window pairs, prescaled by 0.5*WNORM
__device__ float2 g_rec[FREQ];         // cis(-pi*k/480)
__device__ float  g_erb[T_MAX * NB_ERB];
__device__ float  g_mag[T_MAX * NB_DF];
__device__ float  g_carryE[CHUNKS * NB_ERB];
__device__ float  g_inE[CHUNKS * NB_ERB];
__device__ float  g_carryS[CHUNKS * NB_DF];
__device__ float  g_inS[CHUNKS * NB_DF];

__constant__ int c_bandOff[NB_ERB] =
 {0,2,4,6,8,10,12,14,16,18,20,22,24,26,31,36,43,50,58,68,80,93,108,126,146,170,198,229,266,308,358,414};
__constant__ int c_bandCnt[NB_ERB] =
 {2,2,2,2,2,2,2,2,2,2,2,2,2,5,5,7,7,8,10,12,13,15,18,20,24,28,31,37,42,50,56,67};

// ---------------- complex helpers ----------------
__device__ __forceinline__ float2 cmul(float2 a, float2 b){
    return make_float2(fmaf(a.x,b.x,-a.y*b.y), fmaf(a.x,b.y, a.y*b.x));
}

// Winograd radix-3
__device__ __forceinline__ void dft3w(float2 x0, float2 x1, float2 x2,
                                      float2& X0, float2& X1, float2& X2){
    float t1x = x1.x + x2.x, t1y = x1.y + x2.y;
    float t2x = x1.x - x2.x, t2y = x1.y - x2.y;
    X0 = make_float2(x0.x + t1x, x0.y + t1y);
    float mx = fmaf(-0.5f, t1x, x0.x), my = fmaf(-0.5f, t1y, x0.y);
    float vx = 0.86602540378f * t2x,   vy = 0.86602540378f * t2y;
    X1 = make_float2(mx + vy, my - vx);
    X2 = make_float2(mx - vy, my + vx);
}
// Winograd radix-5
__device__ __forceinline__ void dft5w(float2 x0, float2 x1, float2 x2, float2 x3, float2 x4,
                                      float2& X0, float2& X1, float2& X2, float2& X3, float2& X4){
    const float s1 = 0.95105651630f, s2 = 0.58778525229f;
    float t1x=x1.x+x4.x, t1y=x1.y+x4.y;
    float t2x=x1.x-x4.x, t2y=x1.y-x4.y;
    float t3x=x2.x+x3.x, t3y=x2.y+x3.y;
    float t4x=x2.x-x3.x, t4y=x2.y-x3.y;
    float t5x=t1x+t3x,   t5y=t1y+t3y;
    X0 = make_float2(x0.x+t5x, x0.y+t5y);
    float px = fmaf(-0.25f,t5x,x0.x), py = fmaf(-0.25f,t5y,x0.y);
    float t6x=t1x-t3x,   t6y=t1y-t3y;
    float qx = 0.55901699437f*t6x,    qy = 0.55901699437f*t6y;
    float Px=px+qx, Py=py+qy, Qx=px-qx, Qy=py-qy;
    float Rx = fmaf(s2,t4x, s1*t2x),  Ry = fmaf(s2,t4y, s1*t2y);
    float Sx = fmaf(-s1,t4x, s2*t2x), Sy = fmaf(-s1,t4y, s2*t2y);
    X1 = make_float2(Px+Ry, Py-Rx);
    X4 = make_float2(Px-Ry, Py+Rx);
    X2 = make_float2(Qx+Sy, Qy-Sx);
    X3 = make_float2(Qx-Sy, Qy+Sx);
}

// ---------------- init tables ----------------
__global__ void init_tables(){
    int tid = blockIdx.x * blockDim.x + threadIdx.x;
    int nth = gridDim.x * blockDim.x;
    for (int idx = tid; idx < 15*32; idx += nth){
        int k1 = idx / 32, l = idx % 32;
        float ang = -2.0f * PI_F * (float)(l * k1) / 480.0f;
        float sv, cv; sincosf(ang, &sv, &cv);
        g_tw480[idx] = make_float2(cv, sv);
    }
    for (int idx = tid; idx < 4*32; idx += nth){
        int j = idx / 32, l = idx % 32;
        int h = 16 >> j;
        float sv = 0.f, cv = 1.f;
        if (l & h){
            float ang = -2.0f * PI_F * (float)(l & (h-1)) / (float)(2*h);
            sincosf(ang, &sv, &cv);
        }
        g_shtw[idx] = make_float2(cv, sv);
    }
    for (int j = tid; j < NHALF; j += nth){
        float a0 = sinf(0.5f * PI_F * (2*j + 0.5f) / 480.0f);
        float a1 = sinf(0.5f * PI_F * (2*j + 1.5f) / 480.0f);
        const float s = 0.5f * WNORM_F;
        g_win2[j] = make_float2(s * sinf(0.5f * PI_F * a0 * a0),
                                s * sinf(0.5f * PI_F * a1 * a1));
    }
    for (int k = tid; k < FREQ; k += nth){
        float ang = -PI_F * (float)k / 480.0f;
        float sv, cv; sincosf(ang, &sv, &cv);
        g_rec[k] = make_float2(cv, sv);
    }
}

// ---------------- FFT: one warp per frame, register-resident ----------------
__global__ __launch_bounds__(128) void fft_kernel(const float* __restrict__ audio,
                                                  float* __restrict__ out, int T){
    __shared__ float2 sZ[4][NHALF];
    __shared__ float  smag[4][FREQ];
    int w = threadIdx.x >> 5;
    int l = threadIdx.x & 31;
    int t = blockIdx.x * 4 + w;
    if (t >= T) return;

    const float2* audio2 = (const float2*)audio;
    long base2 = ((long)t - 1) * 240;

    // load + window (scale folded)
    float2 z[15];
    #pragma unroll
    for (int m = 0; m < 15; m++){
        long i2 = base2 + l + 32*m;
        float2 x = (i2 >= 0) ? audio2[i2] : make_float2(0.f,0.f);
        float2 ww = g_win2[l + 32*m];
        z[m] = make_float2(x.x*ww.x, x.y*ww.y);
    }

    // ---- radix-15 (3x5 Winograd) in registers
    float2 B[15];
    {
        float2 G0[5], G1[5], G2[5];
        #pragma unroll
        for (int b = 0; b < 5; b++)
            dft3w(z[b], z[5+b], z[10+b], G0[b], G1[b], G2[b]);
        dft5w(G0[0],G0[1],G0[2],G0[3],G0[4], B[0],B[3],B[6],B[9],B[12]);
        G1[1] = cmul(G1[1], make_float2( 0.91354545764f,-0.40673664308f));
        G1[2] = cmul(G1[2], make_float2( 0.66913060636f,-0.74314482548f));
        G1[3] = cmul(G1[3], make_float2( 0.30901699437f,-0.95105651630f));
        G1[4] = cmul(G1[4], make_float2(-0.10452846327f,-0.99452189537f));
        dft5w(G1[0],G1[1],G1[2],G1[3],G1[4], B[1],B[4],B[7],B[10],B[13]);
        G2[1] = cmul(G2[1], make_float2( 0.66913060636f,-0.74314482548f));
        G2[2] = cmul(G2[2], make_float2(-0.10452846327f,-0.99452189537f));
        G2[3] = cmul(G2[3], make_float2(-0.80901699437f,-0.58778525229f));
        G2[4] = cmul(G2[4], make_float2(-0.97814760073f, 0.20791169082f));
        dft5w(G2[0],G2[1],G2[2],G2[3],G2[4], B[2],B[5],B[8],B[11],B[14]);
    }

    // ---- four-step twiddle
    #pragma unroll
    for (int k1 = 1; k1 < 15; k1++)
        B[k1] = cmul(B[k1], g_tw480[k1*32 + l]);

    // ---- 32-pt cross-lane DFT: 5 radix-2 DIF shuffle stages (stage 5 twiddle = identity)
    #pragma unroll
    for (int j = 0; j < 5; j++){
        int h = 16 >> j;
        float sgn = (l & h) ? -1.f : 1.f;
        float2 tw = (j < 4) ? g_shtw[j*32 + l] : make_float2(1.f, 0.f);
        #pragma unroll
        for (int k1 = 0; k1 < 15; k1++){
            float px = __shfl_xor_sync(0xffffffffu, B[k1].x, h);
            float py = __shfl_xor_sync(0xffffffffu, B[k1].y, h);
            float2 nv = make_float2(fmaf(sgn, B[k1].x, px), fmaf(sgn, B[k1].y, py));
            B[k1] = (j < 4) ? cmul(nv, tw) : nv;
        }
    }

    // lane l holds Z[k1 + 15*bitrev5(l)]
    int s = ((l&1)<<4) | ((l&2)<<2) | (l&4) | ((l&8)>>2) | ((l&16)>>4);
    float2* Z = sZ[w];
    #pragma unroll
    for (int k1 = 0; k1 < 15; k1++) Z[15*s + k1] = B[k1];
    __syncwarp();

    // ---- paired real-FFT recombination: k and 480-k together
    float* mg = smag[w];
    float2* out2 = (float2*)out;
    size_t orow = (size_t)t * FREQ;
    for (int k = l; k <= 240; k += 32){
        float2 Zk = Z[k];
        float2 Zc = Z[(480 - k) % 480];
        float Ex = Zk.x + Zc.x, Ey = Zk.y - Zc.y;
        float Ox = Zk.y + Zc.y, Oy = Zc.x - Zk.x;
        float2 rc = g_rec[k];
        float wOx = fmaf(rc.x, Ox, -rc.y*Oy);
        float wOy = fmaf(rc.x, Oy,  rc.y*Ox);
        float X1x = Ex + wOx, X1y = Ey + wOy;           // X[k]
        float X2x = Ex - wOx, X2y = wOy - Ey;           // X[480-k] = conj(E - wO)
        out2[orow + k]       = make_float2(X1x, X1y);
        out2[orow + 480 - k] = make_float2(X2x, X2y);
        float m1 = fmaf(X1x, X1x, X1y*X1y);
        float m2 = fmaf(X2x, X2x, X2y*X2y);
        mg[k]       = m1;
        mg[480 - k] = m2;
        if (k < NB_DF) g_mag[(size_t)t * NB_DF + k] = sqrtf(m1);
    }
    __syncwarp();

    // ---- erb bands
    {
        int st = c_bandOff[l], n = c_bandCnt[l];
        float acc = 0.0f;
        for (int q = 0; q < n; q++) acc += mg[st + q];
        g_erb[(size_t)t * NB_ERB + l] = 10.0f * log10f(acc / (float)n + 1e-10f);
    }
}

// ---------------- fused chunked scans ----------------
__global__ void pass1(int T){
    int w = blockIdx.x * blockDim.x + threadIdx.x;
    int len = T / CHUNKS;
    int totE = CHUNKS * NB_ERB;
    if (w < totE){
        int ch = w % NB_ERB, c = w / NB_ERB;
        const float* x = g_erb + (size_t)c * len * NB_ERB + ch;
        float s = 0.0f;
        for (int i = 0; i < len; i++) s = ALPHA_F * s + ONE_MINUS_ALPHA * x[i * NB_ERB];
        g_carryE[c * NB_ERB + ch] = s;
    } else if (w < totE + CHUNKS * NB_DF){
        int w2 = w - totE;
        int ch = w2 % NB_DF, c = w2 / NB_DF;
        const float* x = g_mag + (size_t)c * len * NB_DF + ch;
        float u = 0.0f;
        for (int i = 0; i < len; i++) u = ALPHA_F * u + ONE_MINUS_ALPHA * x[i * NB_DF];
        g_carryS[c * NB_DF + ch] = u;
    }
}

// parallel affine scan across chunks
__global__ __launch_bounds__(CHUNKS) void pass2(int T){
    __shared__ float sa[CHUNKS];
    __shared__ float sb[CHUNKS];
    int ch = blockIdx.x;
    int c  = threadIdx.x;
    int len = T / CHUNKS;
    float m = __powf(ALPHA_F, (float)len);
    bool isErb = (ch < NB_ERB);
    int cc = isErb ? ch : (ch - NB_ERB);
    float carry = isErb ? g_carryE[c * NB_ERB + cc] : g_carryS[c * NB_DF + cc];

    float a = m, b = carry;
    sa[c] = a; sb[c] = b;
    __syncthreads();
    #pragma unroll
    for (int off = 1; off < CHUNKS; off <<= 1){
        float pa = 0.f, pb = 0.f;
        if (c >= off){ pa = sa[c - off]; pb = sb[c - off]; }
        __syncthreads();
        if (c >= off){ b = a * pb + b; a = a * pa; }
        sa[c] = a; sb[c] = b;
        __syncthreads();
    }
    float Aex = (c == 0) ? 1.f : sa[c-1];
    float Bex = (c == 0) ? 0.f : sb[c-1];
    if (isErb){
        float s0 = -60.0f - 30.0f * (float)cc / 31.0f;
        g_inE[c * NB_ERB + cc] = Aex * s0 + Bex;
    } else {
        float u0 = 0.001f - 0.0009f * (float)cc / 95.0f;
        g_inS[c * NB_DF + cc] = Aex * u0 + Bex;
    }
}

__global__ void pass3(float* __restrict__ out, int T){
    int w = blockIdx.x * blockDim.x + threadIdx.x;
    int len = T / CHUNKS;
    int totE = CHUNKS * NB_ERB;
    if (w < totE){
        int ch = w % NB_ERB, c = w / NB_ERB;
        size_t erb_off = (size_t)T * 962;
        const float* x = g_erb + (size_t)c * len * NB_ERB + ch;
        float* o = out + erb_off + (size_t)c * len * NB_ERB + ch;
        float s = g_inE[c * NB_ERB + ch];
        for (int i = 0; i < len; i++){
            float xv = x[i * NB_ERB];
            s = ALPHA_F * s + ONE_MINUS_ALPHA * xv;
            o[i * NB_ERB] = (xv - s) * 0.025f;
        }
    } else if (w < totE + CHUNKS * NB_DF){
        int w2 = w - totE;
        int ch = w2 % NB_DF, c = w2 / NB_DF;
        size_t sf_off = (size_t)T * 962 + (size_t)T * NB_ERB;
        const float* mgp = g_mag + (size_t)c * len * NB_DF + ch;
        const float* sp = out + (size_t)c * len * 962 + 2 * ch;
        float* o = out + sf_off + (size_t)c * len * 192 + 2 * ch;
        float u = g_inS[c * NB_DF + ch];
        for (int i = 0; i < len; i++){
            u = ALPHA_F * u + ONE_MINUS_ALPHA * mgp[i * NB_DF];
            float r = rsqrtf(u);
            o[i * 192]     = sp[i * 962]     * r;
            o[i * 192 + 1] = sp[i * 962 + 1] * r;
        }
    }
}

// ---------------- launch ----------------
extern "C" void kernel_launch(void* const* d_in, const int* in_sizes, int n_in,
                              void* d_out, int out_size){
    const float* audio = (const float*)d_in[0];
    float* out = (float*)d_out;
    int T = in_sizes[0] / FRAME;
    if (T > T_MAX) T = T_MAX;
    int scanThreads = CHUNKS * (NB_ERB + NB_DF);

    init_tables<<<8, 256>>>();
    fft_kernel<<<(T + 3) / 4, 128>>>(audio, out, T);
    pass1<<<(scanThreads + 255) / 256, 256>>>(T);
    pass2<<<NB_ERB + NB_DF, CHUNKS>>>(T);
    pass3<<<(scanThreads + 255) / 256, 256>>>(out, T);
}